// round 16
// baseline (speedup 1.0000x reference)
#include <cuda_runtime.h>
#include <math.h>

typedef unsigned long long ull;

#define T_DIM 64
#define B_DIM 4
#define INP_DIM 768
#define Q_DIM 384
#define E_DIM 384
#define DFF_DIM 1536
#define ROWS 256          // T*B
#define S1_COLS 1920      // 384 forget + 1536 parts

#define S1_SPLIT 2
#define PROJ_SPLIT 3
#define UP_SPLIT 3
#define DOWN_SPLIT 6

#define N_CHUNKS 4
#define CHUNK_L 16        // N_CHUNKS * CHUNK_L == T_DIM

#define QSPLIT 3
#define QPC (Q_DIM / QSPLIT)   // 128 q per carry CTA
#define QPW (QPC / 8)          // 16 q per carry warp

// ---------------- scratch (device globals; no allocation) ----------------
__device__ float g_forget[ROWS * Q_DIM];
__device__ float g_query[ROWS * Q_DIM];
__device__ float g_keyv[ROWS * Q_DIM];
__device__ float g_value[ROWS * E_DIM];
__device__ float g_out[ROWS * E_DIM];
__device__ float g_hn[ROWS * INP_DIM];
__device__ float g_gate[ROWS * DFF_DIM];
__device__ float g_p1[S1_SPLIT][ROWS][S1_COLS];
__device__ float g_p2[PROJ_SPLIT][ROWS][INP_DIM];
__device__ float g_p3[2 * UP_SPLIT][ROWS][DFF_DIM];
__device__ float g_p4[DOWN_SPLIT][ROWS][INP_DIM];
// scan chunk scratch
__device__ float g_qa[ROWS * Q_DIM];
__device__ float g_P[B_DIM * N_CHUNKS * Q_DIM];
__device__ float g_send[B_DIM * N_CHUNKS * Q_DIM * E_DIM];

// ---------------- helpers ----------------
__device__ __forceinline__ float sigmoidf_(float x) { return 1.f / (1.f + expf(-x)); }
__device__ __forceinline__ float elu1f_(float x) { return x > 0.f ? x + 1.f : expf(x); }

__device__ __forceinline__ ull ffma2(ull a, ull b, ull c) {
    ull d;
    asm("fma.rn.f32x2 %0, %1, %2, %3;" : "=l"(d) : "l"(a), "l"(b), "l"(c));
    return d;
}
__device__ __forceinline__ ull pack2(float lo, float hi) {
    ull d;
    asm("mov.b64 %0, {%1, %2};" : "=l"(d) : "f"(lo), "f"(hi));
    return d;
}
__device__ __forceinline__ void unpack2(ull v, float& lo, float& hi) {
    asm("mov.b64 {%0, %1}, %2;" : "=f"(lo), "=f"(hi) : "l"(v));
}

// ---------------- A-fetch functors for gemm_tile128 ----------------
struct FetchPlain {
    const float* A;
    int lda;
    __device__ __forceinline__ float4 operator()(int row, int k) const {
        return *(const float4*)(A + (size_t)row * lda + k);
    }
};
// computes mixed = mu*inp + (1-mu)*lasts on the fly (row = global row index)
struct FetchMixed {
    const float* inp;
    const float* isf;
    const float* init_inp;
    const float* mu;
    __device__ __forceinline__ float4 operator()(int row, int k) const {
        int t = row >> 2;
        int b = row & 3;
        float m = (t == 0) ? 1.f : isf[row];
        float4 x = *(const float4*)(inp + (size_t)row * INP_DIM + k);
        float4 iv = *(const float4*)(init_inp + (size_t)b * INP_DIM + k);
        float4 pv = (t == 0) ? make_float4(0.f, 0.f, 0.f, 0.f)
                             : *(const float4*)(inp + (size_t)(row - B_DIM) * INP_DIM + k);
        float4 mv = *(const float4*)(mu + k);
        float4 o;
        float lx = pv.x + m * (iv.x - pv.x);
        float ly = pv.y + m * (iv.y - pv.y);
        float lz = pv.z + m * (iv.z - pv.z);
        float lw = pv.w + m * (iv.w - pv.w);
        o.x = mv.x * x.x + (1.f - mv.x) * lx;
        o.y = mv.y * x.y + (1.f - mv.y) * ly;
        o.z = mv.z * x.z + (1.f - mv.z) * lz;
        o.w = mv.w * x.w + (1.f - mv.w) * lw;
        return o;
    }
};

// ---------------- 64x64 f32x2 GEMM tile (proj) ----------------
struct GemmSmem {
    __align__(16) float As[2][16][68];
    __align__(16) float Bs[2][16][64];
};

__device__ __forceinline__ void gemm_tile(
    GemmSmem& sm,
    const float* __restrict__ A, int lda,
    const float* __restrict__ B, int ldb,
    int row0, int col0, int kOff, int nt,
    float* __restrict__ C, int ldc) {
    int tid = threadIdx.x;
    int tx = tid & 15, ty = tid >> 4;
    int ar = tid >> 2, akc = (tid & 3) << 2;
    int br = tid >> 4, bc = (tid & 15) << 2;

    const float* Ap = A + (size_t)(row0 + ar) * lda + kOff + akc;
    const float* Bp = B + (size_t)(kOff + br) * ldb + col0 + bc;

    float4 av = *(const float4*)Ap;
    float4 bv = *(const float4*)Bp;
    sm.As[0][akc + 0][ar] = av.x;
    sm.As[0][akc + 1][ar] = av.y;
    sm.As[0][akc + 2][ar] = av.z;
    sm.As[0][akc + 3][ar] = av.w;
    *(float4*)&sm.Bs[0][br][bc] = bv;
    __syncthreads();

    ull acc[2][4];
#pragma unroll
    for (int p = 0; p < 2; p++)
#pragma unroll
        for (int j = 0; j < 4; j++) acc[p][j] = pack2(0.f, 0.f);

    for (int t = 0; t < nt; t++) {
        int cur = t & 1;
        if (t + 1 < nt) {
            av = *(const float4*)(Ap + (t + 1) * 16);
            bv = *(const float4*)(Bp + (size_t)(t + 1) * 16 * ldb);
        }
#pragma unroll
        for (int k = 0; k < 16; k++) {
            ull a01 = *(const ull*)&sm.As[cur][k][ty << 2];
            ull a23 = *(const ull*)&sm.As[cur][k][(ty << 2) + 2];
            float4 b = *(const float4*)&sm.Bs[cur][k][tx << 2];
            ull b0 = pack2(b.x, b.x);
            ull b1 = pack2(b.y, b.y);
            ull b2 = pack2(b.z, b.z);
            ull b3 = pack2(b.w, b.w);
            acc[0][0] = ffma2(a01, b0, acc[0][0]);
            acc[1][0] = ffma2(a23, b0, acc[1][0]);
            acc[0][1] = ffma2(a01, b1, acc[0][1]);
            acc[1][1] = ffma2(a23, b1, acc[1][1]);
            acc[0][2] = ffma2(a01, b2, acc[0][2]);
            acc[1][2] = ffma2(a23, b2, acc[1][2]);
            acc[0][3] = ffma2(a01, b3, acc[0][3]);
            acc[1][3] = ffma2(a23, b3, acc[1][3]);
        }
        if (t + 1 < nt) {
            int nx = cur ^ 1;
            sm.As[nx][akc + 0][ar] = av.x;
            sm.As[nx][akc + 1][ar] = av.y;
            sm.As[nx][akc + 2][ar] = av.z;
            sm.As[nx][akc + 3][ar] = av.w;
            *(float4*)&sm.Bs[nx][br][bc] = bv;
        }
        __syncthreads();
    }

#pragma unroll
    for (int j = 0; j < 4; j++) {
        int cc = col0 + (tx << 2) + j;
        float lo, hi;
        unpack2(acc[0][j], lo, hi);
        C[(size_t)(row0 + (ty << 2) + 0) * ldc + cc] = lo;
        C[(size_t)(row0 + (ty << 2) + 1) * ldc + cc] = hi;
        unpack2(acc[1][j], lo, hi);
        C[(size_t)(row0 + (ty << 2) + 2) * ldc + cc] = lo;
        C[(size_t)(row0 + (ty << 2) + 3) * ldc + cc] = hi;
    }
}

// ---------------- 128x64 f32x2 GEMM tile (templated A fetch) -------------
struct GemmSmem128 {
    __align__(16) float As[2][16][132];
    __align__(16) float Bs[2][16][64];
};

template <class FetchA>
__device__ __forceinline__ void gemm_tile128(
    GemmSmem128& sm, FetchA fetchA,
    const float* __restrict__ B, int ldb,
    int row0, int col0, int kOff, int nt,
    float* __restrict__ C, int ldc) {
    int tid = threadIdx.x;
    int tx = tid & 15, ty = tid >> 4;
    int ar = tid >> 1, akb = (tid & 1) << 3;
    int br = tid >> 4, bc = (tid & 15) << 2;

    int arow = row0 + ar;
    const float* Bp = B + (size_t)(kOff + br) * ldb + col0 + bc;

    float4 a0 = fetchA(arow, kOff + akb);
    float4 a1 = fetchA(arow, kOff + akb + 4);
    float4 bv = *(const float4*)Bp;
    sm.As[0][akb + 0][ar] = a0.x;
    sm.As[0][akb + 1][ar] = a0.y;
    sm.As[0][akb + 2][ar] = a0.z;
    sm.As[0][akb + 3][ar] = a0.w;
    sm.As[0][akb + 4][ar] = a1.x;
    sm.As[0][akb + 5][ar] = a1.y;
    sm.As[0][akb + 6][ar] = a1.z;
    sm.As[0][akb + 7][ar] = a1.w;
    *(float4*)&sm.Bs[0][br][bc] = bv;
    __syncthreads();

    ull acc[4][4];
#pragma unroll
    for (int p = 0; p < 4; p++)
#pragma unroll
        for (int j = 0; j < 4; j++) acc[p][j] = pack2(0.f, 0.f);

    for (int t = 0; t < nt; t++) {
        int cur = t & 1;
        if (t + 1 < nt) {
            a0 = fetchA(arow, kOff + (t + 1) * 16 + akb);
            a1 = fetchA(arow, kOff + (t + 1) * 16 + akb + 4);
            bv = *(const float4*)(Bp + (size_t)(t + 1) * 16 * ldb);
        }
#pragma unroll
        for (int k = 0; k < 16; k++) {
            ull A0 = *(const ull*)&sm.As[cur][k][(ty << 3) + 0];
            ull A1 = *(const ull*)&sm.As[cur][k][(ty << 3) + 2];
            ull A2 = *(const ull*)&sm.As[cur][k][(ty << 3) + 4];
            ull A3 = *(const ull*)&sm.As[cur][k][(ty << 3) + 6];
            float4 b = *(const float4*)&sm.Bs[cur][k][tx << 2];
            ull b0 = pack2(b.x, b.x);
            ull b1 = pack2(b.y, b.y);
            ull b2 = pack2(b.z, b.z);
            ull b3 = pack2(b.w, b.w);
            acc[0][0] = ffma2(A0, b0, acc[0][0]);
            acc[1][0] = ffma2(A1, b0, acc[1][0]);
            acc[2][0] = ffma2(A2, b0, acc[2][0]);
            acc[3][0] = ffma2(A3, b0, acc[3][0]);
            acc[0][1] = ffma2(A0, b1, acc[0][1]);
            acc[1][1] = ffma2(A1, b1, acc[1][1]);
            acc[2][1] = ffma2(A2, b1, acc[2][1]);
            acc[3][1] = ffma2(A3, b1, acc[3][1]);
            acc[0][2] = ffma2(A0, b2, acc[0][2]);
            acc[1][2] = ffma2(A1, b2, acc[1][2]);
            acc[2][2] = ffma2(A2, b2, acc[2][2]);
            acc[3][2] = ffma2(A3, b2, acc[3][2]);
            acc[0][3] = ffma2(A0, b3, acc[0][3]);
            acc[1][3] = ffma2(A1, b3, acc[1][3]);
            acc[2][3] = ffma2(A2, b3, acc[2][3]);
            acc[3][3] = ffma2(A3, b3, acc[3][3]);
        }
        if (t + 1 < nt) {
            int nx = cur ^ 1;
            sm.As[nx][akb + 0][ar] = a0.x;
            sm.As[nx][akb + 1][ar] = a0.y;
            sm.As[nx][akb + 2][ar] = a0.z;
            sm.As[nx][akb + 3][ar] = a0.w;
            sm.As[nx][akb + 4][ar] = a1.x;
            sm.As[nx][akb + 5][ar] = a1.y;
            sm.As[nx][akb + 6][ar] = a1.z;
            sm.As[nx][akb + 7][ar] = a1.w;
            *(float4*)&sm.Bs[nx][br][bc] = bv;
        }
        __syncthreads();
    }

#pragma unroll
    for (int p = 0; p < 4; p++) {
        int rr = row0 + (ty << 3) + (p << 1);
#pragma unroll
        for (int j = 0; j < 4; j++) {
            int cc = col0 + (tx << 2) + j;
            float lo, hi;
            unpack2(acc[p][j], lo, hi);
            C[(size_t)(rr + 0) * ldc + cc] = lo;
            C[(size_t)(rr + 1) * ldc + cc] = hi;
        }
    }
}

// ---------------- stage1 (mixed fused into A-fetch for mix_W part) -------
__global__ __launch_bounds__(256) void stage1_kernel(const float* __restrict__ inp,
                                                     const float* __restrict__ isf,
                                                     const float* __restrict__ init_inp,
                                                     const float* __restrict__ mix_mu,
                                                     const float* __restrict__ mix_W,
                                                     const float* __restrict__ layer_W) {
    __shared__ GemmSmem128 sm;
    int bx = blockIdx.x, row0 = blockIdx.y * 128, z = blockIdx.z;
    int kOff = z * (INP_DIM / S1_SPLIT);
    const int nt = (INP_DIM / S1_SPLIT) / 16;
    float* C = &g_p1[z][0][0];
    if (bx < Q_DIM / 64) {
        FetchMixed fa{inp, isf, init_inp, mix_mu};
        gemm_tile128(sm, fa, mix_W, Q_DIM, row0, bx * 64, kOff, nt, C, S1_COLS);
    } else {
        FetchPlain fa{inp, INP_DIM};
        gemm_tile128(sm, fa, layer_W, 1536, row0, (bx - Q_DIM / 64) * 64, kOff, nt,
                     C + Q_DIM, S1_COLS);
    }
}

// ---------------- epi1 ----------------
__global__ void epi1_kernel(const float* __restrict__ drops) {
    int r = blockIdx.x, j = threadIdx.x;
    float d = drops[r];
    const float* p0 = &g_p1[0][r][0];
    const float* p1 = &g_p1[1][r][0];
    float fs = p0[j] + p1[j];
    g_forget[r * Q_DIM + j] = (sigmoidf_(fs) - 1.f) * d + 1.f;
    float qs = (p0[384 + j] + p1[384 + j]) * d;
    g_query[r * Q_DIM + j] = elu1f_(qs);
    float ks = (p0[768 + j] + p1[768 + j]) * d;
    g_keyv[r * Q_DIM + j] = elu1f_(ks);
    float rs = (p0[1152 + j] + p1[1152 + j]) * d;
    float vs = (p0[1536 + j] + p1[1536 + j]) * d;
    g_value[r * E_DIM + j] = sigmoidf_(rs) * vs;
}

// ---------------- scan pass 1: per-chunk local scan, 4 CTAs/SM -----------
__global__ __launch_bounds__(128, 4) void scan_chunk_kernel(
    const float* __restrict__ isf, const float* __restrict__ init_state) {
    int b = blockIdx.y, c = blockIdx.z;
    int tid = threadIdx.x, lane = tid & 31, w = tid >> 5;
    int ebase = blockIdx.x * 16 + w * 4;
    bool writer = (blockIdx.x == 0) && (w == 0) && (c > 0);
    int t0 = c * CHUNK_L;

    float s[12][4];
    float a[12];
#pragma unroll
    for (int kk = 0; kk < 12; kk++) {
        a[kk] = 1.f;
#pragma unroll
        for (int j = 0; j < 4; j++) s[kk][j] = 0.f;
    }

    for (int l = 0; l < CHUNK_L; l++) {
        int tg = t0 + l;
        int r = tg * B_DIM + b;
        float f[12], k[12], q[12];
        const float* fp = g_forget + (size_t)r * Q_DIM + lane;
        const float* kp = g_keyv + (size_t)r * Q_DIM + lane;
        const float* qp = g_query + (size_t)r * Q_DIM + lane;
#pragma unroll
        for (int kk = 0; kk < 12; kk++) {
            f[kk] = fp[32 * kk];
            k[kk] = kp[32 * kk];
            q[kk] = qp[32 * kk];
        }
        float4 v = *(const float4*)(g_value + (size_t)r * E_DIM + ebase);
        float m = isf[r];
        bool rst = (tg == 0) || (m > 0.f);
        if (rst) {
#pragma unroll
            for (int kk = 0; kk < 12; kk++) {
                int qi = lane + 32 * kk;
                float4 iv =
                    *(const float4*)(init_state + ((size_t)b * Q_DIM + qi) * E_DIM + ebase);
                s[kk][0] = iv.x; s[kk][1] = iv.y; s[kk][2] = iv.z; s[kk][3] = iv.w;
            }
        }
        float o0 = 0.f, o1 = 0.f, o2 = 0.f, o3 = 0.f;
#pragma unroll
        for (int kk = 0; kk < 12; kk++) {
            float ff = f[kk], kv = k[kk], qr = q[kk];
            a[kk] = rst ? 0.f : a[kk] * ff;
            float n0 = fmaf(ff, s[kk][0], kv * v.x); s[kk][0] = n0; o0 = fmaf(qr, n0, o0);
            float n1 = fmaf(ff, s[kk][1], kv * v.y); s[kk][1] = n1; o1 = fmaf(qr, n1, o1);
            float n2 = fmaf(ff, s[kk][2], kv * v.z); s[kk][2] = n2; o2 = fmaf(qr, n2, o2);
            float n3 = fmaf(ff, s[kk][3], kv * v.w); s[kk][3] = n3; o3 = fmaf(qr, n3, o3);
        }
#pragma unroll
        for (int off = 16; off; off >>= 1) {
            o0 += __shfl_xor_sync(0xffffffffu, o0, off);
            o1 += __shfl_xor_sync(0xffffffffu, o1, off);
            o2 += __shfl_xor_sync(0xffffffffu, o2, off);
            o3 += __shfl_xor_sync(0xffffffffu, o3, off);
        }
        if (lane == 0) {
            float* op = g_out + (size_t)r * E_DIM + ebase;
            op[0] = o0; op[1] = o1; op[2] = o2; op[3] = o3;
        }
        if (writer) {
#pragma unroll
            for (int kk = 0; kk < 12; kk++)
                g_qa[(size_t)r * Q_DIM + lane + 32 * kk] = q[kk] * a[kk];
        }
    }

    if (c < N_CHUNKS - 1) {
        size_t base = ((size_t)(b * N_CHUNKS + c) * Q_DIM) * E_DIM;
#pragma unroll
        for (int kk = 0; kk < 12; kk++) {
            int qi = lane + 32 * kk;
            float4 sv = make_float4(s[kk][0], s[kk][1], s[kk][2], s[kk][3]);
            *(float4*)(g_send + base + (size_t)qi * E_DIM + ebase) = sv;
        }
        if ((blockIdx.x == 0) && (w == 0)) {
#pragma unroll
            for (int kk = 0; kk < 12; kk++)
                g_P[(b * N_CHUNKS + c) * Q_DIM + lane + 32 * kk] = a[kk];
        }
    }
}

// ---------------- fused carry: combine + correction, prefetched ----------
__global__ __launch_bounds__(256) void carry_kernel() {
    __shared__ __align__(16) float qa_s[CHUNK_L][QPC];   // 8 KB
    __shared__ float part[8][CHUNK_L][32];               // 16 KB
    int b = blockIdx.z, qs = blockIdx.y;
    int lane = threadIdx.x & 31;
    int w = threadIdx.x >> 5;
    int e = blockIdx.x * 32 + lane;
    int q0 = qs * QPC + w * QPW;

    float S[QPW];
    float spv[QPW];
#pragma unroll
    for (int i = 0; i < QPW; i++) S[i] = 0.f;

    {
        const float* sp = g_send + ((size_t)(b * N_CHUNKS + 0) * Q_DIM + q0) * E_DIM + e;
#pragma unroll
        for (int i = 0; i < QPW; i++) spv[i] = sp[(size_t)i * E_DIM];
    }

    for (int c = 0; c < N_CHUNKS - 1; c++) {
        const float* pp = g_P + (b * N_CHUNKS + c) * Q_DIM + q0;
#pragma unroll
        for (int i = 0; i < QPW; i++)
            S[i] = fmaf(pp[i], S[i], spv[i]);

        if (c + 1 < N_CHUNKS - 1) {
            const float* sp =
                g_send + ((size_t)(b * N_CHUNKS + c + 1) * Q_DIM + q0) * E_DIM + e;
#pragma unroll
            for (int i = 0; i < QPW; i++) spv[i] = sp[(size_t)i * E_DIM];
        }

        __syncthreads();
        for (int idx = threadIdx.x; idx < CHUNK_L * QPC; idx += 256) {
            int l = idx / QPC, j = idx - l * QPC;
            qa_s[l][j] =
                g_qa[(size_t)(((c + 1) * CHUNK_L + l) * B_DIM + b) * Q_DIM + qs * QPC + j];
        }
        __syncthreads();

        float acc[CHUNK_L];
#pragma unroll
        for (int t = 0; t < CHUNK_L; t++) acc[t] = 0.f;
#pragma unroll
        for (int i = 0; i < QPW; i += 4) {
#pragma unroll
            for (int t = 0; t < CHUNK_L; t++) {
                float4 qa4 = *(const float4*)&qa_s[t][w * QPW + i];
                acc[t] = fmaf(qa4.x, S[i + 0], acc[t]);
                acc[t] = fmaf(qa4.y, S[i + 1], acc[t]);
                acc[t] = fmaf(qa4.z, S[i + 2], acc[t]);
                acc[t] = fmaf(qa4.w, S[i + 3], acc[t]);
            }
        }
#pragma unroll
        for (int t = 0; t < CHUNK_L; t++) part[w][t][lane] = acc[t];
        __syncthreads();
        {
            int tb = threadIdx.x >> 5, el = threadIdx.x & 31;
#pragma unroll
            for (int h = 0; h < 2; h++) {
                int t = tb + h * 8;
                float ssum = 0.f;
#pragma unroll
                for (int ww = 0; ww < 8; ww++) ssum += part[ww][t][el];
                atomicAdd(&g_out[(size_t)(((c + 1) * CHUNK_L + t) * B_DIM + b) * E_DIM +
                                 blockIdx.x * 32 + el],
                          ssum);
            }
        }
    }
}

// ---------------- RMS norm ----------------
__global__ __launch_bounds__(128) void rms_kernel(const float* __restrict__ rms_w) {
    int r = blockIdx.x;
    int tid = threadIdx.x;
    int lane = tid & 31, wid = tid >> 5;
    __shared__ float red[4];
    float ss = 0.f;
    for (int i = tid; i < E_DIM; i += 128) {
        float v = g_out[r * E_DIM + i];
        ss += v * v;
    }
#pragma unroll
    for (int off = 16; off; off >>= 1) ss += __shfl_xor_sync(0xffffffffu, ss, off);
    if (lane == 0) red[wid] = ss;
    __syncthreads();
    if (tid == 0) red[0] = rsqrtf((red[0] + red[1] + red[2] + red[3]) * (1.f / E_DIM) + 1e-6f);
    __syncthreads();
    float scale = red[0];
    for (int i = tid; i < E_DIM; i += 128)
        g_out[r * E_DIM + i] = g_out[r * E_DIM + i] * scale * rms_w[i];
}

// ---------------- proj GEMM partials (1 full wave: 144 CTAs) -------------
__global__ __launch_bounds__(256) void proj_kernel(const float* __restrict__ proj_W) {
    __shared__ GemmSmem sm;
    int z = blockIdx.z;
    gemm_tile(sm, g_out, E_DIM, proj_W, INP_DIM, blockIdx.y * 64, blockIdx.x * 64,
              z * (E_DIM / PROJ_SPLIT), (E_DIM / PROJ_SPLIT) / 16, &g_p2[z][0][0], INP_DIM);
}

// ---------------- projLN ----------------
__global__ __launch_bounds__(256) void projln_kernel(const float* __restrict__ inp,
                                                     const float* __restrict__ ln_w,
                                                     const float* __restrict__ ln_b) {
    __shared__ float sh[INP_DIM];
    __shared__ float red1[8], red2[8], stats[2];
    int r = blockIdx.x, tid = threadIdx.x, lane = tid & 31, wid = tid >> 5;
    float s1 = 0.f, s2 = 0.f;
    for (int c = tid; c < INP_DIM; c += 256) {
        float h = g_p2[0][r][c] + g_p2[1][r][c] + g_p2[2][r][c] + inp[r * INP_DIM + c];
        sh[c] = h;
        s1 += h;
        s2 += h * h;
    }
#pragma unroll
    for (int off = 16; off; off >>= 1) {
        s1 += __shfl_xor_sync(0xffffffffu, s1, off);
        s2 += __shfl_xor_sync(0xffffffffu, s2, off);
    }
    if (lane == 0) { red1[wid] = s1; red2[wid] = s2; }
    __syncthreads();
    if (tid == 0) {
        float t1 = 0.f, t2 = 0.f;
        for (int w = 0; w < 8; w++) { t1 += red1[w]; t2 += red2[w]; }
        float mu = t1 * (1.f / INP_DIM);
        float var = t2 * (1.f / INP_DIM) - mu * mu;
        stats[0] = mu;
        stats[1] = rsqrtf(var + 1e-5f);
    }
    __syncthreads();
    float mu = stats[0], inv = stats[1];
    for (int c = tid; c < INP_DIM; c += 256)
        g_hn[r * INP_DIM + c] = (sh[c] - mu) * inv * ln_w[c] + ln_b[c];
}

// ---------------- FFN up partials (2 full waves: 288 CTAs) ---------------
__global__ __launch_bounds__(256) void ffnup_kernel(const float* __restrict__ W1,
                                                    const float* __restrict__ W2) {
    __shared__ GemmSmem128 sm;
    int z = blockIdx.z;
    int which = z / UP_SPLIT, sp = z % UP_SPLIT;
    const float* B = which ? W2 : W1;
    FetchPlain fa{g_hn, INP_DIM};
    gemm_tile128(sm, fa, B, DFF_DIM, blockIdx.y * 128, blockIdx.x * 64,
                 sp * (INP_DIM / UP_SPLIT), (INP_DIM / UP_SPLIT) / 16, &g_p3[z][0][0], DFF_DIM);
}

// ---------------- silu-mul reduce (float4) ----------------
__global__ void silumul_kernel() {
    int i = blockIdx.x * blockDim.x + threadIdx.x;
    const float4* b = (const float4*)&g_p3[0][0][0];
    const size_t st = (size_t)ROWS * DFF_DIM / 4;
    float4 u = b[i], g = b[UP_SPLIT * st + i];
#pragma unroll
    for (int z = 1; z < UP_SPLIT; z++) {
        float4 uu = b[z * st + i];
        float4 gg = b[(UP_SPLIT + z) * st + i];
        u.x += uu.x; u.y += uu.y; u.z += uu.z; u.w += uu.w;
        g.x += gg.x; g.y += gg.y; g.z += gg.z; g.w += gg.w;
    }
    float4 o;
    o.x = u.x * (1.f / (1.f + expf(-u.x))) * g.x;
    o.y = u.y * (1.f / (1.f + expf(-u.y))) * g.y;
    o.z = u.z * (1.f / (1.f + expf(-u.z))) * g.z;
    o.w = u.w * (1.f / (1.f + expf(-u.w))) * g.w;
    ((float4*)g_gate)[i] = o;
}

// ---------------- down GEMM partials ----------------
__global__ __launch_bounds__(256) void down_kernel(const float* __restrict__ W3) {
    __shared__ GemmSmem128 sm;
    int z = blockIdx.z;
    FetchPlain fa{g_gate, DFF_DIM};
    gemm_tile128(sm, fa, W3, INP_DIM, blockIdx.y * 128, blockIdx.x * 64,
                 z * (DFF_DIM / DOWN_SPLIT), (DFF_DIM / DOWN_SPLIT) / 16, &g_p4[z][0][0],
                 INP_DIM);
}

// ---------------- final reduce (float4) ----------------
__global__ void reduceout_kernel(float* __restrict__ out) {
    int i = blockIdx.x * blockDim.x + threadIdx.x;
    const float4* b = (const float4*)&g_p4[0][0][0];
    const size_t st = (size_t)ROWS * INP_DIM / 4;
    float4 s = b[i];
#pragma unroll
    for (int z = 1; z < DOWN_SPLIT; z++) {
        float4 v = b[z * st + i];
        s.x += v.x; s.y += v.y; s.z += v.z; s.w += v.w;
    }
    ((float4*)out)[i] = s;
}

// ---------------- launch ----------------
extern "C" void kernel_launch(void* const* d_in, const int* in_sizes, int n_in,
                              void* d_out, int out_size) {
    const float* inp        = (const float*)d_in[0];
    const float* is_first   = (const float*)d_in[1];
    const float* drops      = (const float*)d_in[2];
    const float* init_inp   = (const float*)d_in[3];
    const float* init_state = (const float*)d_in[4];
    const float* mix_mu     = (const float*)d_in[5];
    const float* mix_W      = (const float*)d_in[6];
    const float* layer_W    = (const float*)d_in[7];
    const float* proj_W     = (const float*)d_in[8];
    const float* rms_w      = (const float*)d_in[9];
    const float* ln_w       = (const float*)d_in[10];
    const float* ln_b       = (const float*)d_in[11];
    const float* ffn_W1     = (const float*)d_in[12];
    const float* ffn_W2     = (const float*)d_in[13];
    const float* ffn_W3     = (const float*)d_in[14];
    float* out = (float*)d_out;

    stage1_kernel<<<dim3(30, ROWS / 128, S1_SPLIT), 256>>>(inp, is_first, init_inp, mix_mu,
                                                           mix_W, layer_W);
    epi1_kernel<<<ROWS, 384>>>(drops);

    scan_chunk_kernel<<<dim3(E_DIM / 16, B_DIM, N_CHUNKS), 128>>>(is_first, init_state);
    carry_kernel<<<dim3(E_DIM / 32, QSPLIT, B_DIM), 256>>>();

    rms_kernel<<<ROWS, 128>>>(rms_w);
    proj_kernel<<<dim3(INP_DIM / 64, ROWS / 64, PROJ_SPLIT), 256>>>(proj_W);
    projln_kernel<<<ROWS, 256>>>(inp, ln_w, ln_b);
    ffnup_kernel<<<dim3(DFF_DIM / 64, ROWS / 128, 2 * UP_SPLIT), 256>>>(ffn_W1, ffn_W2);
    silumul_kernel<<<(ROWS * DFF_DIM / 4) / 256, 256>>>();
    down_kernel<<<dim3(INP_DIM / 64, ROWS / 128, DOWN_SPLIT), 256>>>(ffn_W3);
    reduceout_kernel<<<(ROWS * INP_DIM / 4) / 256, 256>>>(out);
}

// round 17
// speedup vs baseline: 1.0721x; 1.0721x over previous
#include <cuda_runtime.h>
#include <math.h>

typedef unsigned long long ull;

#define T_DIM 64
#define B_DIM 4
#define INP_DIM 768
#define Q_DIM 384
#define E_DIM 384
#define DFF_DIM 1536
#define ROWS 256          // T*B
#define S1_COLS 1920      // 384 forget + 1536 parts

#define S1_SPLIT 2
#define PROJ_SPLIT 3
#define UP_SPLIT 3
#define DOWN_SPLIT 6

#define N_CHUNKS 4
#define CHUNK_L 16        // N_CHUNKS * CHUNK_L == T_DIM

#define QSPLIT 4
#define QPC (Q_DIM / QSPLIT)   // 96 q per carry CTA
#define QPW (QPC / 8)          // 12 q per carry warp

// ---------------- scratch (device globals; no allocation) ----------------
__device__ float g_mixed[ROWS * INP_DIM];
__device__ float g_forget[ROWS * Q_DIM];
__device__ float g_query[ROWS * Q_DIM];
__device__ float g_keyv[ROWS * Q_DIM];
__device__ float g_value[ROWS * E_DIM];
__device__ float g_out[ROWS * E_DIM];
__device__ float g_hn[ROWS * INP_DIM];
__device__ float g_gate[ROWS * DFF_DIM];
__device__ float g_p1[S1_SPLIT][ROWS][S1_COLS];
__device__ float g_p2[PROJ_SPLIT][ROWS][INP_DIM];
__device__ float g_p3[2 * UP_SPLIT][ROWS][DFF_DIM];
// scan chunk scratch
__device__ float g_qa[ROWS * Q_DIM];
__device__ float g_P[B_DIM * N_CHUNKS * Q_DIM];
__device__ float g_send[B_DIM * N_CHUNKS * Q_DIM * E_DIM];

// ---------------- helpers ----------------
__device__ __forceinline__ float sigmoidf_(float x) { return 1.f / (1.f + expf(-x)); }
__device__ __forceinline__ float elu1f_(float x) { return x > 0.f ? x + 1.f : expf(x); }

__device__ __forceinline__ ull ffma2(ull a, ull b, ull c) {
    ull d;
    asm("fma.rn.f32x2 %0, %1, %2, %3;" : "=l"(d) : "l"(a), "l"(b), "l"(c));
    return d;
}
__device__ __forceinline__ ull pack2(float lo, float hi) {
    ull d;
    asm("mov.b64 %0, {%1, %2};" : "=l"(d) : "f"(lo), "f"(hi));
    return d;
}
__device__ __forceinline__ void unpack2(ull v, float& lo, float& hi) {
    asm("mov.b64 {%0, %1}, %2;" : "=f"(lo), "=f"(hi) : "l"(v));
}

// ---------------- K0: mixed (float4) ----------------
__global__ void mixed_kernel(const float* __restrict__ inp,
                             const float* __restrict__ isf,
                             const float* __restrict__ init_inp,
                             const float* __restrict__ mu) {
    int r = blockIdx.x;
    int t = r >> 2;
    int b = r & 3;
    float m = (t == 0) ? 1.f : isf[r];
    int c4 = threadIdx.x;
    const float4* xp = (const float4*)(inp + (size_t)r * INP_DIM) + c4;
    const float4* pp = (const float4*)(inp + (size_t)(r - B_DIM) * INP_DIM) + c4;
    const float4* ip = (const float4*)(init_inp + (size_t)b * INP_DIM) + c4;
    const float4* mp = (const float4*)mu + c4;
    float4 x = *xp;
    float4 iv = *ip;
    float4 pv = (t == 0) ? make_float4(0.f, 0.f, 0.f, 0.f) : *pp;
    float4 mv = *mp;
    float4 o;
    float lx = pv.x + m * (iv.x - pv.x);
    float ly = pv.y + m * (iv.y - pv.y);
    float lz = pv.z + m * (iv.z - pv.z);
    float lw = pv.w + m * (iv.w - pv.w);
    o.x = mv.x * x.x + (1.f - mv.x) * lx;
    o.y = mv.y * x.y + (1.f - mv.y) * ly;
    o.z = mv.z * x.z + (1.f - mv.z) * lz;
    o.w = mv.w * x.w + (1.f - mv.w) * lw;
    ((float4*)(g_mixed + (size_t)r * INP_DIM))[c4] = o;
}

// ---------------- 64x64 f32x2 GEMM tile (proj) ----------------
struct GemmSmem {
    __align__(16) float As[2][16][68];
    __align__(16) float Bs[2][16][64];
};

__device__ __forceinline__ void gemm_tile(
    GemmSmem& sm,
    const float* __restrict__ A, int lda,
    const float* __restrict__ B, int ldb,
    int row0, int col0, int kOff, int nt,
    float* __restrict__ C, int ldc) {
    int tid = threadIdx.x;
    int tx = tid & 15, ty = tid >> 4;
    int ar = tid >> 2, akc = (tid & 3) << 2;
    int br = tid >> 4, bc = (tid & 15) << 2;

    const float* Ap = A + (size_t)(row0 + ar) * lda + kOff + akc;
    const float* Bp = B + (size_t)(kOff + br) * ldb + col0 + bc;

    float4 av = *(const float4*)Ap;
    float4 bv = *(const float4*)Bp;
    sm.As[0][akc + 0][ar] = av.x;
    sm.As[0][akc + 1][ar] = av.y;
    sm.As[0][akc + 2][ar] = av.z;
    sm.As[0][akc + 3][ar] = av.w;
    *(float4*)&sm.Bs[0][br][bc] = bv;
    __syncthreads();

    ull acc[2][4];
#pragma unroll
    for (int p = 0; p < 2; p++)
#pragma unroll
        for (int j = 0; j < 4; j++) acc[p][j] = pack2(0.f, 0.f);

    for (int t = 0; t < nt; t++) {
        int cur = t & 1;
        if (t + 1 < nt) {
            av = *(const float4*)(Ap + (t + 1) * 16);
            bv = *(const float4*)(Bp + (size_t)(t + 1) * 16 * ldb);
        }
#pragma unroll
        for (int k = 0; k < 16; k++) {
            ull a01 = *(const ull*)&sm.As[cur][k][ty << 2];
            ull a23 = *(const ull*)&sm.As[cur][k][(ty << 2) + 2];
            float4 b = *(const float4*)&sm.Bs[cur][k][tx << 2];
            ull b0 = pack2(b.x, b.x);
            ull b1 = pack2(b.y, b.y);
            ull b2 = pack2(b.z, b.z);
            ull b3 = pack2(b.w, b.w);
            acc[0][0] = ffma2(a01, b0, acc[0][0]);
            acc[1][0] = ffma2(a23, b0, acc[1][0]);
            acc[0][1] = ffma2(a01, b1, acc[0][1]);
            acc[1][1] = ffma2(a23, b1, acc[1][1]);
            acc[0][2] = ffma2(a01, b2, acc[0][2]);
            acc[1][2] = ffma2(a23, b2, acc[1][2]);
            acc[0][3] = ffma2(a01, b3, acc[0][3]);
            acc[1][3] = ffma2(a23, b3, acc[1][3]);
        }
        if (t + 1 < nt) {
            int nx = cur ^ 1;
            sm.As[nx][akc + 0][ar] = av.x;
            sm.As[nx][akc + 1][ar] = av.y;
            sm.As[nx][akc + 2][ar] = av.z;
            sm.As[nx][akc + 3][ar] = av.w;
            *(float4*)&sm.Bs[nx][br][bc] = bv;
        }
        __syncthreads();
    }

#pragma unroll
    for (int j = 0; j < 4; j++) {
        int cc = col0 + (tx << 2) + j;
        float lo, hi;
        unpack2(acc[0][j], lo, hi);
        C[(size_t)(row0 + (ty << 2) + 0) * ldc + cc] = lo;
        C[(size_t)(row0 + (ty << 2) + 1) * ldc + cc] = hi;
        unpack2(acc[1][j], lo, hi);
        C[(size_t)(row0 + (ty << 2) + 2) * ldc + cc] = lo;
        C[(size_t)(row0 + (ty << 2) + 3) * ldc + cc] = hi;
    }
}

// ---------------- 128x64 f32x2 GEMM tile (optional atomic epilogue) ------
struct GemmSmem128 {
    __align__(16) float As[2][16][132];
    __align__(16) float Bs[2][16][64];
};

template <bool ATOMIC>
__device__ __forceinline__ void gemm_tile128(
    GemmSmem128& sm,
    const float* __restrict__ A, int lda,
    const float* __restrict__ B, int ldb,
    int row0, int col0, int kOff, int nt,
    float* __restrict__ C, int ldc) {
    int tid = threadIdx.x;
    int tx = tid & 15, ty = tid >> 4;
    int ar = tid >> 1, akb = (tid & 1) << 3;
    int br = tid >> 4, bc = (tid & 15) << 2;

    const float* Ap = A + (size_t)(row0 + ar) * lda + kOff + akb;
    const float* Bp = B + (size_t)(kOff + br) * ldb + col0 + bc;

    float4 a0 = *(const float4*)Ap;
    float4 a1 = *(const float4*)(Ap + 4);
    float4 bv = *(const float4*)Bp;
    sm.As[0][akb + 0][ar] = a0.x;
    sm.As[0][akb + 1][ar] = a0.y;
    sm.As[0][akb + 2][ar] = a0.z;
    sm.As[0][akb + 3][ar] = a0.w;
    sm.As[0][akb + 4][ar] = a1.x;
    sm.As[0][akb + 5][ar] = a1.y;
    sm.As[0][akb + 6][ar] = a1.z;
    sm.As[0][akb + 7][ar] = a1.w;
    *(float4*)&sm.Bs[0][br][bc] = bv;
    __syncthreads();

    ull acc[4][4];
#pragma unroll
    for (int p = 0; p < 4; p++)
#pragma unroll
        for (int j = 0; j < 4; j++) acc[p][j] = pack2(0.f, 0.f);

    for (int t = 0; t < nt; t++) {
        int cur = t & 1;
        if (t + 1 < nt) {
            a0 = *(const float4*)(Ap + (t + 1) * 16);
            a1 = *(const float4*)(Ap + (t + 1) * 16 + 4);
            bv = *(const float4*)(Bp + (size_t)(t + 1) * 16 * ldb);
        }
#pragma unroll
        for (int k = 0; k < 16; k++) {
            ull A0 = *(const ull*)&sm.As[cur][k][(ty << 3) + 0];
            ull A1 = *(const ull*)&sm.As[cur][k][(ty << 3) + 2];
            ull A2 = *(const ull*)&sm.As[cur][k][(ty << 3) + 4];
            ull A3 = *(const ull*)&sm.As[cur][k][(ty << 3) + 6];
            float4 b = *(const float4*)&sm.Bs[cur][k][tx << 2];
            ull b0 = pack2(b.x, b.x);
            ull b1 = pack2(b.y, b.y);
            ull b2 = pack2(b.z, b.z);
            ull b3 = pack2(b.w, b.w);
            acc[0][0] = ffma2(A0, b0, acc[0][0]);
            acc[1][0] = ffma2(A1, b0, acc[1][0]);
            acc[2][0] = ffma2(A2, b0, acc[2][0]);
            acc[3][0] = ffma2(A3, b0, acc[3][0]);
            acc[0][1] = ffma2(A0, b1, acc[0][1]);
            acc[1][1] = ffma2(A1, b1, acc[1][1]);
            acc[2][1] = ffma2(A2, b1, acc[2][1]);
            acc[3][1] = ffma2(A3, b1, acc[3][1]);
            acc[0][2] = ffma2(A0, b2, acc[0][2]);
            acc[1][2] = ffma2(A1, b2, acc[1][2]);
            acc[2][2] = ffma2(A2, b2, acc[2][2]);
            acc[3][2] = ffma2(A3, b2, acc[3][2]);
            acc[0][3] = ffma2(A0, b3, acc[0][3]);
            acc[1][3] = ffma2(A1, b3, acc[1][3]);
            acc[2][3] = ffma2(A2, b3, acc[2][3]);
            acc[3][3] = ffma2(A3, b3, acc[3][3]);
        }
        if (t + 1 < nt) {
            int nx = cur ^ 1;
            sm.As[nx][akb + 0][ar] = a0.x;
            sm.As[nx][akb + 1][ar] = a0.y;
            sm.As[nx][akb + 2][ar] = a0.z;
            sm.As[nx][akb + 3][ar] = a0.w;
            sm.As[nx][akb + 4][ar] = a1.x;
            sm.As[nx][akb + 5][ar] = a1.y;
            sm.As[nx][akb + 6][ar] = a1.z;
            sm.As[nx][akb + 7][ar] = a1.w;
            *(float4*)&sm.Bs[nx][br][bc] = bv;
        }
        __syncthreads();
    }

#pragma unroll
    for (int p = 0; p < 4; p++) {
        int rr = row0 + (ty << 3) + (p << 1);
#pragma unroll
        for (int j = 0; j < 4; j++) {
            int cc = col0 + (tx << 2) + j;
            float lo, hi;
            unpack2(acc[p][j], lo, hi);
            if (ATOMIC) {
                atomicAdd(&C[(size_t)(rr + 0) * ldc + cc], lo);
                atomicAdd(&C[(size_t)(rr + 1) * ldc + cc], hi);
            } else {
                C[(size_t)(rr + 0) * ldc + cc] = lo;
                C[(size_t)(rr + 1) * ldc + cc] = hi;
            }
        }
    }
}

// ---------------- stage1 ----------------
__global__ __launch_bounds__(256) void stage1_kernel(const float* __restrict__ inp,
                                                     const float* __restrict__ mix_W,
                                                     const float* __restrict__ layer_W) {
    __shared__ GemmSmem128 sm;
    int bx = blockIdx.x, row0 = blockIdx.y * 128, z = blockIdx.z;
    int kOff = z * (INP_DIM / S1_SPLIT);
    const int nt = (INP_DIM / S1_SPLIT) / 16;
    float* C = &g_p1[z][0][0];
    if (bx < Q_DIM / 64)
        gemm_tile128<false>(sm, g_mixed, INP_DIM, mix_W, Q_DIM, row0, bx * 64, kOff, nt, C,
                            S1_COLS);
    else
        gemm_tile128<false>(sm, inp, INP_DIM, layer_W, 1536, row0, (bx - Q_DIM / 64) * 64, kOff,
                            nt, C + Q_DIM, S1_COLS);
}

// ---------------- epi1 ----------------
__global__ void epi1_kernel(const float* __restrict__ drops) {
    int r = blockIdx.x, j = threadIdx.x;
    float d = drops[r];
    const float* p0 = &g_p1[0][r][0];
    const float* p1 = &g_p1[1][r][0];
    float fs = p0[j] + p1[j];
    g_forget[r * Q_DIM + j] = (sigmoidf_(fs) - 1.f) * d + 1.f;
    float qs = (p0[384 + j] + p1[384 + j]) * d;
    g_query[r * Q_DIM + j] = elu1f_(qs);
    float ks = (p0[768 + j] + p1[768 + j]) * d;
    g_keyv[r * Q_DIM + j] = elu1f_(ks);
    float rs = (p0[1152 + j] + p1[1152 + j]) * d;
    float vs = (p0[1536 + j] + p1[1536 + j]) * d;
    g_value[r * E_DIM + j] = sigmoidf_(rs) * vs;
}

// ---------------- scan pass 1: per-chunk local scan, 4 CTAs/SM -----------
__global__ __launch_bounds__(128, 4) void scan_chunk_kernel(
    const float* __restrict__ isf, const float* __restrict__ init_state) {
    int b = blockIdx.y, c = blockIdx.z;
    int tid = threadIdx.x, lane = tid & 31, w = tid >> 5;
    int ebase = blockIdx.x * 16 + w * 4;
    bool writer = (blockIdx.x == 0) && (w == 0) && (c > 0);
    int t0 = c * CHUNK_L;

    float s[12][4];
    float a[12];
#pragma unroll
    for (int kk = 0; kk < 12; kk++) {
        a[kk] = 1.f;
#pragma unroll
        for (int j = 0; j < 4; j++) s[kk][j] = 0.f;
    }

    for (int l = 0; l < CHUNK_L; l++) {
        int tg = t0 + l;
        int r = tg * B_DIM + b;
        float f[12], k[12], q[12];
        const float* fp = g_forget + (size_t)r * Q_DIM + lane;
        const float* kp = g_keyv + (size_t)r * Q_DIM + lane;
        const float* qp = g_query + (size_t)r * Q_DIM + lane;
#pragma unroll
        for (int kk = 0; kk < 12; kk++) {
            f[kk] = fp[32 * kk];
            k[kk] = kp[32 * kk];
            q[kk] = qp[32 * kk];
        }
        float4 v = *(const float4*)(g_value + (size_t)r * E_DIM + ebase);
        float m = isf[r];
        bool rst = (tg == 0) || (m > 0.f);
        if (rst) {
#pragma unroll
            for (int kk = 0; kk < 12; kk++) {
                int qi = lane + 32 * kk;
                float4 iv =
                    *(const float4*)(init_state + ((size_t)b * Q_DIM + qi) * E_DIM + ebase);
                s[kk][0] = iv.x; s[kk][1] = iv.y; s[kk][2] = iv.z; s[kk][3] = iv.w;
            }
        }
        float o0 = 0.f, o1 = 0.f, o2 = 0.f, o3 = 0.f;
#pragma unroll
        for (int kk = 0; kk < 12; kk++) {
            float ff = f[kk], kv = k[kk], qr = q[kk];
            a[kk] = rst ? 0.f : a[kk] * ff;
            float n0 = fmaf(ff, s[kk][0], kv * v.x); s[kk][0] = n0; o0 = fmaf(qr, n0, o0);
            float n1 = fmaf(ff, s[kk][1], kv * v.y); s[kk][1] = n1; o1 = fmaf(qr, n1, o1);
            float n2 = fmaf(ff, s[kk][2], kv * v.z); s[kk][2] = n2; o2 = fmaf(qr, n2, o2);
            float n3 = fmaf(ff, s[kk][3], kv * v.w); s[kk][3] = n3; o3 = fmaf(qr, n3, o3);
        }
#pragma unroll
        for (int off = 16; off; off >>= 1) {
            o0 += __shfl_xor_sync(0xffffffffu, o0, off);
            o1 += __shfl_xor_sync(0xffffffffu, o1, off);
            o2 += __shfl_xor_sync(0xffffffffu, o2, off);
            o3 += __shfl_xor_sync(0xffffffffu, o3, off);
        }
        if (lane == 0) {
            float* op = g_out + (size_t)r * E_DIM + ebase;
            op[0] = o0; op[1] = o1; op[2] = o2; op[3] = o3;
        }
        if (writer) {
#pragma unroll
            for (int kk = 0; kk < 12; kk++)
                g_qa[(size_t)r * Q_DIM + lane + 32 * kk] = q[kk] * a[kk];
        }
    }

    if (c < N_CHUNKS - 1) {
        size_t base = ((size_t)(b * N_CHUNKS + c) * Q_DIM) * E_DIM;
#pragma unroll
        for (int kk = 0; kk < 12; kk++) {
            int qi = lane + 32 * kk;
            float4 sv = make_float4(s[kk][0], s[kk][1], s[kk][2], s[kk][3]);
            *(float4*)(g_send + base + (size_t)qi * E_DIM + ebase) = sv;
        }
        if ((blockIdx.x == 0) && (w == 0)) {
#pragma unroll
            for (int kk = 0; kk < 12; kk++)
                g_P[(b * N_CHUNKS + c) * Q_DIM + lane + 32 * kk] = a[kk];
        }
    }
}

// ---------------- fused carry: combine + correction, prefetched ----------
__global__ __launch_bounds__(256) void carry_kernel() {
    __shared__ __align__(16) float qa_s[CHUNK_L][QPC];
    __shared__ float part[8][CHUNK_L][32];
    int b = blockIdx.z, qs = blockIdx.y;
    int lane = threadIdx.x & 31;
    int w = threadIdx.x >> 5;
    int e = blockIdx.x * 32 + lane;
    int q0 = qs * QPC + w * QPW;

    float S[QPW];
    float spv[QPW];
#pragma unroll
    for (int i = 0; i < QPW; i++) S[i] = 0.f;

    {
        const float* sp = g_send + ((size_t)(b * N_CHUNKS + 0) * Q_DIM + q0) * E_DIM + e;
#pragma unroll
        for (int i = 0; i < QPW; i++) spv[i] = sp[(size_t)i * E_DIM];
    }

    for (int c = 0; c < N_CHUNKS - 1; c++) {
        const float* pp = g_P + (b * N_CHUNKS + c) * Q_DIM + q0;
#pragma unroll
        for (int i = 0; i < QPW; i++)
            S[i] = fmaf(pp[i], S[i], spv[i]);

        if (c + 1 < N_CHUNKS - 1) {
            const float* sp =
                g_send + ((size_t)(b * N_CHUNKS + c + 1) * Q_DIM + q0) * E_DIM + e;
#pragma unroll
            for (int i = 0; i < QPW; i++) spv[i] = sp[(size_t)i * E_DIM];
        }

        __syncthreads();
        for (int idx = threadIdx.x; idx < CHUNK_L * QPC; idx += 256) {
            int l = idx / QPC, j = idx - l * QPC;
            qa_s[l][j] =
                g_qa[(size_t)(((c + 1) * CHUNK_L + l) * B_DIM + b) * Q_DIM + qs * QPC + j];
        }
        __syncthreads();

        float acc[CHUNK_L];
#pragma unroll
        for (int t = 0; t < CHUNK_L; t++) acc[t] = 0.f;
#pragma unroll
        for (int i = 0; i < QPW; i += 4) {
#pragma unroll
            for (int t = 0; t < CHUNK_L; t++) {
                float4 qa4 = *(const float4*)&qa_s[t][w * QPW + i];
                acc[t] = fmaf(qa4.x, S[i + 0], acc[t]);
                acc[t] = fmaf(qa4.y, S[i + 1], acc[t]);
                acc[t] = fmaf(qa4.z, S[i + 2], acc[t]);
                acc[t] = fmaf(qa4.w, S[i + 3], acc[t]);
            }
        }
#pragma unroll
        for (int t = 0; t < CHUNK_L; t++) part[w][t][lane] = acc[t];
        __syncthreads();
        {
            int tb = threadIdx.x >> 5, el = threadIdx.x & 31;
#pragma unroll
            for (int h = 0; h < 2; h++) {
                int t = tb + h * 8;
                float ssum = 0.f;
#pragma unroll
                for (int ww = 0; ww < 8; ww++) ssum += part[ww][t][el];
                atomicAdd(&g_out[(size_t)(((c + 1) * CHUNK_L + t) * B_DIM + b) * E_DIM +
                                 blockIdx.x * 32 + el],
                          ssum);
            }
        }
    }
}

// ---------------- RMS norm ----------------
__global__ __launch_bounds__(128) void rms_kernel(const float* __restrict__ rms_w) {
    int r = blockIdx.x;
    int tid = threadIdx.x;
    int lane = tid & 31, wid = tid >> 5;
    __shared__ float red[4];
    float ss = 0.f;
    for (int i = tid; i < E_DIM; i += 128) {
        float v = g_out[r * E_DIM + i];
        ss += v * v;
    }
#pragma unroll
    for (int off = 16; off; off >>= 1) ss += __shfl_xor_sync(0xffffffffu, ss, off);
    if (lane == 0) red[wid] = ss;
    __syncthreads();
    if (tid == 0) red[0] = rsqrtf((red[0] + red[1] + red[2] + red[3]) * (1.f / E_DIM) + 1e-6f);
    __syncthreads();
    float scale = red[0];
    for (int i = tid; i < E_DIM; i += 128)
        g_out[r * E_DIM + i] = g_out[r * E_DIM + i] * scale * rms_w[i];
}

// ---------------- proj GEMM partials (1 full wave: 144 CTAs) -------------
__global__ __launch_bounds__(256) void proj_kernel(const float* __restrict__ proj_W) {
    __shared__ GemmSmem sm;
    int z = blockIdx.z;
    gemm_tile(sm, g_out, E_DIM, proj_W, INP_DIM, blockIdx.y * 64, blockIdx.x * 64,
              z * (E_DIM / PROJ_SPLIT), (E_DIM / PROJ_SPLIT) / 16, &g_p2[z][0][0], INP_DIM);
}

// ---------------- projLN ----------------
__global__ __launch_bounds__(256) void projln_kernel(const float* __restrict__ inp,
                                                     const float* __restrict__ ln_w,
                                                     const float* __restrict__ ln_b) {
    __shared__ float sh[INP_DIM];
    __shared__ float red1[8], red2[8], stats[2];
    int r = blockIdx.x, tid = threadIdx.x, lane = tid & 31, wid = tid >> 5;
    float s1 = 0.f, s2 = 0.f;
    for (int c = tid; c < INP_DIM; c += 256) {
        float h = g_p2[0][r][c] + g_p2[1][r][c] + g_p2[2][r][c] + inp[r * INP_DIM + c];
        sh[c] = h;
        s1 += h;
        s2 += h * h;
    }
#pragma unroll
    for (int off = 16; off; off >>= 1) {
        s1 += __shfl_xor_sync(0xffffffffu, s1, off);
        s2 += __shfl_xor_sync(0xffffffffu, s2, off);
    }
    if (lane == 0) { red1[wid] = s1; red2[wid] = s2; }
    __syncthreads();
    if (tid == 0) {
        float t1 = 0.f, t2 = 0.f;
        for (int w = 0; w < 8; w++) { t1 += red1[w]; t2 += red2[w]; }
        float mu = t1 * (1.f / INP_DIM);
        float var = t2 * (1.f / INP_DIM) - mu * mu;
        stats[0] = mu;
        stats[1] = rsqrtf(var + 1e-5f);
    }
    __syncthreads();
    float mu = stats[0], inv = stats[1];
    for (int c = tid; c < INP_DIM; c += 256)
        g_hn[r * INP_DIM + c] = (sh[c] - mu) * inv * ln_w[c] + ln_b[c];
}

// ---------------- FFN up partials (2 full waves: 288 CTAs) ---------------
__global__ __launch_bounds__(256) void ffnup_kernel(const float* __restrict__ W1,
                                                    const float* __restrict__ W2) {
    __shared__ GemmSmem128 sm;
    int z = blockIdx.z;
    int which = z / UP_SPLIT, sp = z % UP_SPLIT;
    const float* B = which ? W2 : W1;
    gemm_tile128<false>(sm, g_hn, INP_DIM, B, DFF_DIM, blockIdx.y * 128, blockIdx.x * 64,
                        sp * (INP_DIM / UP_SPLIT), (INP_DIM / UP_SPLIT) / 16, &g_p3[z][0][0],
                        DFF_DIM);
}

// ---------------- silu-mul reduce (float4) + zero d_out ------------------
__global__ void silumul_kernel(float* __restrict__ out) {
    int i = blockIdx.x * blockDim.x + threadIdx.x;
    // zero the output buffer (down_kernel accumulates into it atomically)
    if (i < ROWS * INP_DIM / 4)
        ((float4*)out)[i] = make_float4(0.f, 0.f, 0.f, 0.f);
    const float4* b = (const float4*)&g_p3[0][0][0];
    const size_t st = (size_t)ROWS * DFF_DIM / 4;
    float4 u = b[i], g = b[UP_SPLIT * st + i];
#pragma unroll
    for (int z = 1; z < UP_SPLIT; z++) {
        float4 uu = b[z * st + i];
        float4 gg = b[(UP_SPLIT + z) * st + i];
        u.x += uu.x; u.y += uu.y; u.z += uu.z; u.w += uu.w;
        g.x += gg.x; g.y += gg.y; g.z += gg.z; g.w += gg.w;
    }
    float4 o;
    o.x = u.x * (1.f / (1.f + expf(-u.x))) * g.x;
    o.y = u.y * (1.f / (1.f + expf(-u.y))) * g.y;
    o.z = u.z * (1.f / (1.f + expf(-u.z))) * g.z;
    o.w = u.w * (1.f / (1.f + expf(-u.w))) * g.w;
    ((float4*)g_gate)[i] = o;
}

// ---------------- down GEMM: atomic accumulate into d_out ----------------
__global__ __launch_bounds__(256) void down_kernel(const float* __restrict__ W3,
                                                   float* __restrict__ out) {
    __shared__ GemmSmem128 sm;
    int z = blockIdx.z;
    gemm_tile128<true>(sm, g_gate, DFF_DIM, W3, INP_DIM, blockIdx.y * 128, blockIdx.x * 64,
                       z * (DFF_DIM / DOWN_SPLIT), (DFF_DIM / DOWN_SPLIT) / 16, out, INP_DIM);
}

// ---------------- launch ----------------
extern "C" void kernel_launch(void* const* d_in, const int* in_sizes, int n_in,
                              void* d_out, int out_size) {
    const float* inp        = (const float*)d_in[0];
    const float* is_first   = (const float*)d_in[1];
    const float* drops      = (const float*)d_in[2];
    const float* init_inp   = (const float*)d_in[3];
    const float* init_state = (const float*)d_in[4];
    const float* mix_mu     = (const float*)d_in[5];
    const float* mix_W      = (const float*)d_in[6];
    const float* layer_W    = (const float*)d_in[7];
    const float* proj_W     = (const float*)d_in[8];
    const float* rms_w      = (const float*)d_in[9];
    const float* ln_w       = (const float*)d_in[10];
    const float* ln_b       = (const float*)d_in[11];
    const float* ffn_W1     = (const float*)d_in[12];
    const float* ffn_W2     = (const float*)d_in[13];
    const float* ffn_W3     = (const float*)d_in[14];
    float* out = (float*)d_out;

    mixed_kernel<<<ROWS, INP_DIM / 4>>>(inp, is_first, init_inp, mix_mu);
    stage1_kernel<<<dim3(30, ROWS / 128, S1_SPLIT), 256>>>(inp, mix_W, layer_W);
    epi1_kernel<<<ROWS, 384>>>(drops);

    scan_chunk_kernel<<<dim3(E_DIM / 16, B_DIM, N_CHUNKS), 128>>>(is_first, init_state);
    carry_kernel<<<dim3(E_DIM / 32, QSPLIT, B_DIM), 256>>>();

    rms_kernel<<<ROWS, 128>>>(rms_w);
    proj_kernel<<<dim3(INP_DIM / 64, ROWS / 64, PROJ_SPLIT), 256>>>(proj_W);
    projln_kernel<<<ROWS, 256>>>(inp, ln_w, ln_b);
    ffnup_kernel<<<dim3(DFF_DIM / 64, ROWS / 128, 2 * UP_SPLIT), 256>>>(ffn_W1, ffn_W2);
    silumul_kernel<<<(ROWS * DFF_DIM / 4) / 256, 256>>>(out);
    down_kernel<<<dim3(INP_DIM / 64, ROWS / 128, DOWN_SPLIT), 256>>>(ffn_W3, out);
}